// round 2
// baseline (speedup 1.0000x reference)
#include <cuda_runtime.h>

#define BATCH 32
#define HDIM 128
#define WDIM 128
#define CDIM 64
#define N4 262144           // float4 rows per batch = H*W*C/4
#define OUT_PER_BATCH 262144

// scratch: 14 reduction sums per batch (S0..S3, then upper-tri of second moments)
__device__ double g_sums[BATCH][14];
// per-batch output coefficients: w0..w3, offset
__device__ float  g_coef[BATCH][5];

__global__ void zero_kernel() {
    int i = threadIdx.x;
    if (i < BATCH * 14) ((double*)g_sums)[i] = 0.0;
}

__global__ void __launch_bounds__(256) reduce_kernel(const float4* __restrict__ x) {
    int b = blockIdx.y;
    const float4* __restrict__ xb = x + (size_t)b * N4;

    float a0=0.f,a1=0.f,a2=0.f,a3=0.f;
    float q00=0.f,q01=0.f,q02=0.f,q03=0.f;
    float q11=0.f,q12=0.f,q13=0.f;
    float q22=0.f,q23=0.f,q33=0.f;

    int stride = gridDim.x * blockDim.x;
    for (int i = blockIdx.x * blockDim.x + threadIdx.x; i < N4; i += stride) {
        float4 v = __ldg(&xb[i]);
        a0 += v.x; a1 += v.y; a2 += v.z; a3 += v.w;
        q00 = fmaf(v.x, v.x, q00);
        q01 = fmaf(v.x, v.y, q01);
        q02 = fmaf(v.x, v.z, q02);
        q03 = fmaf(v.x, v.w, q03);
        q11 = fmaf(v.y, v.y, q11);
        q12 = fmaf(v.y, v.z, q12);
        q13 = fmaf(v.y, v.w, q13);
        q22 = fmaf(v.z, v.z, q22);
        q23 = fmaf(v.z, v.w, q23);
        q33 = fmaf(v.w, v.w, q33);
    }

    float acc[14] = {a0,a1,a2,a3,q00,q01,q02,q03,q11,q12,q13,q22,q23,q33};

    // warp reduce each of 14 partials
    #pragma unroll
    for (int k = 0; k < 14; k++) {
        #pragma unroll
        for (int off = 16; off > 0; off >>= 1)
            acc[k] += __shfl_down_sync(0xffffffffu, acc[k], off);
    }

    __shared__ double sh[8][14];
    int warp = threadIdx.x >> 5;
    int lane = threadIdx.x & 31;
    if (lane == 0) {
        #pragma unroll
        for (int k = 0; k < 14; k++) sh[warp][k] = (double)acc[k];
    }
    __syncthreads();

    if (threadIdx.x < 14) {
        double s = 0.0;
        int nwarps = (blockDim.x + 31) >> 5;
        for (int w = 0; w < nwarps; w++) s += sh[w][threadIdx.x];
        atomicAdd(&g_sums[b][threadIdx.x], s);
    }
}

__global__ void solve_kernel() {
    int b = threadIdx.x;
    if (b >= BATCH) return;

    double S[14];
    #pragma unroll
    for (int k = 0; k < 14; k++) S[k] = g_sums[b][k];

    const double N = (double)N4;
    double m[4];
    #pragma unroll
    for (int j = 0; j < 4; j++) m[j] = S[j] / N;

    // second moment matrix Q (symmetric)
    double Q[4][4];
    Q[0][0]=S[4];  Q[0][1]=S[5];  Q[0][2]=S[6];  Q[0][3]=S[7];
    Q[1][1]=S[8];  Q[1][2]=S[9];  Q[1][3]=S[10];
    Q[2][2]=S[11]; Q[2][3]=S[12]; Q[3][3]=S[13];
    Q[1][0]=Q[0][1]; Q[2][0]=Q[0][2]; Q[3][0]=Q[0][3];
    Q[2][1]=Q[1][2]; Q[3][1]=Q[1][3]; Q[3][2]=Q[2][3];

    double inv_s[4];
    #pragma unroll
    for (int j = 0; j < 4; j++) {
        double var = Q[j][j] / N - m[j] * m[j];
        inv_s[j] = (var > 0.0) ? 1.0 / sqrt(var) : 0.0;
    }

    // gram of normalized columns
    double A[4][4];
    #pragma unroll
    for (int i = 0; i < 4; i++)
        #pragma unroll
        for (int j = 0; j < 4; j++)
            A[i][j] = (Q[i][j] - N * m[i] * m[j]) * inv_s[i] * inv_s[j];

    // cyclic Jacobi eigen-decomposition (4x4 symmetric, fp64)
    double V[4][4] = {{1,0,0,0},{0,1,0,0},{0,0,1,0},{0,0,0,1}};
    for (int sweep = 0; sweep < 12; sweep++) {
        for (int p = 0; p < 3; p++) {
            for (int q = p + 1; q < 4; q++) {
                double apq = A[p][q];
                if (fabs(apq) < 1e-300) continue;
                double theta = (A[q][q] - A[p][p]) / (2.0 * apq);
                double t = copysign(1.0, theta) / (fabs(theta) + sqrt(theta * theta + 1.0));
                double c = 1.0 / sqrt(t * t + 1.0);
                double s = t * c;
                double tau = s / (1.0 + c);
                for (int r = 0; r < 4; r++) {
                    if (r == p || r == q) continue;
                    double g = A[r][p], h = A[r][q];
                    A[r][p] = A[p][r] = g - s * (h + tau * g);
                    A[r][q] = A[q][r] = h + s * (g - tau * h);
                }
                A[p][p] -= t * apq;
                A[q][q] += t * apq;
                A[p][q] = A[q][p] = 0.0;
                for (int r = 0; r < 4; r++) {
                    double g = V[r][p], h = V[r][q];
                    V[r][p] = g - s * (h + tau * g);
                    V[r][q] = h + s * (g - tau * h);
                }
            }
        }
    }

    // top eigenvector = column with max diagonal eigenvalue
    int k = 0;
    double best = A[0][0];
    #pragma unroll
    for (int j = 1; j < 4; j++) if (A[j][j] > best) { best = A[j][j]; k = j; }

    double v[4];
    #pragma unroll
    for (int j = 0; j < 4; j++) v[j] = V[j][k];
    double sv = v[0] + v[1] + v[2] + v[3];
    if (sv < 0.0) {
        #pragma unroll
        for (int j = 0; j < 4; j++) v[j] = -v[j];
    }

    double w[4], off = 0.0;
    #pragma unroll
    for (int j = 0; j < 4; j++) {
        w[j] = v[j] * inv_s[j];
        off += w[j] * m[j];
    }

    g_coef[b][0] = (float)w[0];
    g_coef[b][1] = (float)w[1];
    g_coef[b][2] = (float)w[2];
    g_coef[b][3] = (float)w[3];
    g_coef[b][4] = (float)off;
}

__global__ void __launch_bounds__(256) out_kernel(const float4* __restrict__ x,
                                                  float* __restrict__ out) {
    int b = blockIdx.y;
    float w0 = g_coef[b][0];
    float w1 = g_coef[b][1];
    float w2 = g_coef[b][2];
    float w3 = g_coef[b][3];
    float off = g_coef[b][4];

    const float4* __restrict__ xb = x + (size_t)b * N4;
    float* __restrict__ ob = out + (size_t)b * OUT_PER_BATCH;

    int stride = gridDim.x * blockDim.x;
    for (int i = blockIdx.x * blockDim.x + threadIdx.x; i < N4; i += stride) {
        float4 v = __ldg(&xb[i]);
        float r = fmaf(v.x, w0, fmaf(v.y, w1, fmaf(v.z, w2, fmaf(v.w, w3, -off))));
        // i = (h*128 + w)*16 + cg
        int cg = i & 15;
        int ww = (i >> 4) & 127;
        int h  = i >> 11;
        int oc = ((h & 1) << 5) | ((ww & 1) << 4) | cg;
        int oidx = (((((h >> 1) << 6) | (ww >> 1)) << 6) | oc);
        ob[oidx] = r;
    }
}

extern "C" void kernel_launch(void* const* d_in, const int* in_sizes, int n_in,
                              void* d_out, int out_size) {
    const float4* x = (const float4*)d_in[0];
    float* out = (float*)d_out;

    zero_kernel<<<1, 448>>>();
    reduce_kernel<<<dim3(64, BATCH), 256>>>(x);
    solve_kernel<<<1, 32>>>();
    out_kernel<<<dim3(64, BATCH), 256>>>(x, out);
}

// round 3
// speedup vs baseline: 1.4602x; 1.4602x over previous
#include <cuda_runtime.h>

#define BATCH 32
#define N4 262144            // float4 rows per batch = 128*128*64/4
#define RBLKS 64             // reduce blocks per batch
#define THREADS 256
#define ITERS (N4 / (RBLKS * THREADS))   // 16

// per-(batch, block) partial sums: S0..S3 then upper-tri second moments (10)
__device__ double g_part[BATCH][RBLKS][14];
// per-batch output coefficients: w0..w3, offset
__device__ float  g_coef[BATCH][8];

__global__ void __launch_bounds__(THREADS) reduce_kernel(const float4* __restrict__ x) {
    int b = blockIdx.y;
    const float4* __restrict__ xb = x + (size_t)b * N4;

    float a0=0.f,a1=0.f,a2=0.f,a3=0.f;
    float q00=0.f,q01=0.f,q02=0.f,q03=0.f;
    float q11=0.f,q12=0.f,q13=0.f;
    float q22=0.f,q23=0.f,q33=0.f;

    int base = blockIdx.x * THREADS + threadIdx.x;
    #pragma unroll 4
    for (int it = 0; it < ITERS; it++) {
        float4 v = __ldg(&xb[base + it * (RBLKS * THREADS)]);
        a0 += v.x; a1 += v.y; a2 += v.z; a3 += v.w;
        q00 = fmaf(v.x, v.x, q00);
        q01 = fmaf(v.x, v.y, q01);
        q02 = fmaf(v.x, v.z, q02);
        q03 = fmaf(v.x, v.w, q03);
        q11 = fmaf(v.y, v.y, q11);
        q12 = fmaf(v.y, v.z, q12);
        q13 = fmaf(v.y, v.w, q13);
        q22 = fmaf(v.z, v.z, q22);
        q23 = fmaf(v.z, v.w, q23);
        q33 = fmaf(v.w, v.w, q33);
    }

    float acc[14] = {a0,a1,a2,a3,q00,q01,q02,q03,q11,q12,q13,q22,q23,q33};

    #pragma unroll
    for (int k = 0; k < 14; k++) {
        #pragma unroll
        for (int off = 16; off > 0; off >>= 1)
            acc[k] += __shfl_down_sync(0xffffffffu, acc[k], off);
    }

    __shared__ double sh[8][14];
    int warp = threadIdx.x >> 5;
    int lane = threadIdx.x & 31;
    if (lane == 0) {
        #pragma unroll
        for (int k = 0; k < 14; k++) sh[warp][k] = (double)acc[k];
    }
    __syncthreads();

    if (threadIdx.x < 14) {
        double s = 0.0;
        #pragma unroll
        for (int w = 0; w < 8; w++) s += sh[w][threadIdx.x];
        g_part[b][blockIdx.x][threadIdx.x] = s;   // no atomics, no pre-zero needed
    }
}

// one block per batch: sum partials, then single-thread 4x4 Jacobi (few rotations)
__global__ void __launch_bounds__(64) solve_kernel() {
    int b = blockIdx.x;
    int t = threadIdx.x;

    __shared__ double sh[RBLKS][14];
    #pragma unroll
    for (int k = 0; k < 14; k++) sh[t][k] = g_part[b][t][k];
    __syncthreads();

    __shared__ double S[14];
    if (t < 14) {
        double s = 0.0;
        #pragma unroll 8
        for (int w = 0; w < RBLKS; w++) s += sh[w][t];
        S[t] = s;
    }
    __syncthreads();

    if (t != 0) return;

    const double N = (double)N4;
    double m[4];
    #pragma unroll
    for (int j = 0; j < 4; j++) m[j] = S[j] / N;

    double Q[4][4];
    Q[0][0]=S[4];  Q[0][1]=S[5];  Q[0][2]=S[6];  Q[0][3]=S[7];
    Q[1][1]=S[8];  Q[1][2]=S[9];  Q[1][3]=S[10];
    Q[2][2]=S[11]; Q[2][3]=S[12]; Q[3][3]=S[13];
    Q[1][0]=Q[0][1]; Q[2][0]=Q[0][2]; Q[3][0]=Q[0][3];
    Q[2][1]=Q[1][2]; Q[3][1]=Q[1][3]; Q[3][2]=Q[2][3];

    double inv_s[4];
    #pragma unroll
    for (int j = 0; j < 4; j++) {
        double var = Q[j][j] / N - m[j] * m[j];
        inv_s[j] = (var > 0.0) ? 1.0 / sqrt(var) : 0.0;
    }

    double A[4][4];
    #pragma unroll
    for (int i = 0; i < 4; i++)
        #pragma unroll
        for (int j = 0; j < 4; j++)
            A[i][j] = (Q[i][j] - N * m[i] * m[j]) * inv_s[i] * inv_s[j];

    // cyclic Jacobi; near-identity gram -> quadratic convergence in ~2-3 sweeps.
    double V[4][4] = {{1,0,0,0},{0,1,0,0},{0,0,1,0},{0,0,0,1}};
    for (int sweep = 0; sweep < 5; sweep++) {
        double offsum = fabs(A[0][1]) + fabs(A[0][2]) + fabs(A[0][3])
                      + fabs(A[1][2]) + fabs(A[1][3]) + fabs(A[2][3]);
        if (offsum < 1e-12) break;
        for (int p = 0; p < 3; p++) {
            for (int q = p + 1; q < 4; q++) {
                double apq = A[p][q];
                if (fabs(apq) < 1e-13) continue;
                double theta = (A[q][q] - A[p][p]) / (2.0 * apq);
                double tt = copysign(1.0, theta) / (fabs(theta) + sqrt(theta * theta + 1.0));
                double c = 1.0 / sqrt(tt * tt + 1.0);
                double s = tt * c;
                double tau = s / (1.0 + c);
                for (int r = 0; r < 4; r++) {
                    if (r == p || r == q) continue;
                    double g = A[r][p], h = A[r][q];
                    A[r][p] = A[p][r] = g - s * (h + tau * g);
                    A[r][q] = A[q][r] = h + s * (g - tau * h);
                }
                A[p][p] -= tt * apq;
                A[q][q] += tt * apq;
                A[p][q] = A[q][p] = 0.0;
                for (int r = 0; r < 4; r++) {
                    double g = V[r][p], h = V[r][q];
                    V[r][p] = g - s * (h + tau * g);
                    V[r][q] = h + s * (g - tau * h);
                }
            }
        }
    }

    int k = 0;
    double best = A[0][0];
    #pragma unroll
    for (int j = 1; j < 4; j++) if (A[j][j] > best) { best = A[j][j]; k = j; }

    double v[4];
    #pragma unroll
    for (int j = 0; j < 4; j++) v[j] = V[j][k];
    double sv = v[0] + v[1] + v[2] + v[3];
    if (sv < 0.0) {
        #pragma unroll
        for (int j = 0; j < 4; j++) v[j] = -v[j];
    }

    double w[4], off = 0.0;
    #pragma unroll
    for (int j = 0; j < 4; j++) {
        w[j] = v[j] * inv_s[j];
        off += w[j] * m[j];
    }

    g_coef[b][0] = (float)w[0];
    g_coef[b][1] = (float)w[1];
    g_coef[b][2] = (float)w[2];
    g_coef[b][3] = (float)w[3];
    g_coef[b][4] = (float)off;
}

__global__ void __launch_bounds__(THREADS) out_kernel(const float4* __restrict__ x,
                                                      float* __restrict__ out) {
    int b = blockIdx.y;
    float w0 = g_coef[b][0];
    float w1 = g_coef[b][1];
    float w2 = g_coef[b][2];
    float w3 = g_coef[b][3];
    float off = g_coef[b][4];

    const float4* __restrict__ xb = x + (size_t)b * N4;
    float* __restrict__ ob = out + (size_t)b * N4;

    int base = blockIdx.x * THREADS + threadIdx.x;
    #pragma unroll 4
    for (int it = 0; it < ITERS; it++) {
        int i = base + it * (RBLKS * THREADS);
        float4 v = __ldg(&xb[i]);
        float r = fmaf(v.x, w0, fmaf(v.y, w1, fmaf(v.z, w2, fmaf(v.w, w3, -off))));
        // i = (h*128 + w)*16 + cg  ->  out[h/2][w/2][(h&1)*32 + (w&1)*16 + cg]
        int cg = i & 15;
        int ww = (i >> 4) & 127;
        int h  = i >> 11;
        int oc = ((h & 1) << 5) | ((ww & 1) << 4) | cg;
        int oidx = (((((h >> 1) << 6) | (ww >> 1)) << 6) | oc);
        ob[oidx] = r;
    }
}

extern "C" void kernel_launch(void* const* d_in, const int* in_sizes, int n_in,
                              void* d_out, int out_size) {
    const float4* x = (const float4*)d_in[0];
    float* out = (float*)d_out;

    reduce_kernel<<<dim3(RBLKS, BATCH), THREADS>>>(x);
    solve_kernel<<<BATCH, 64>>>();
    out_kernel<<<dim3(RBLKS, BATCH), THREADS>>>(x, out);
}

// round 4
// speedup vs baseline: 2.8081x; 1.9232x over previous
#include <cuda_runtime.h>

#define BATCH 32
#define N4 262144            // float4 rows per batch = 128*128*64/4
#define RBLKS 64             // reduce blocks per batch
#define THREADS 256
#define ITERS (N4 / (RBLKS * THREADS))   // 16

// per-(batch, block) partial sums: S0..S3 then upper-tri second moments (10)
__device__ double g_part[BATCH][RBLKS][14];
// per-batch output coefficients: w0..w3, offset
__device__ float  g_coef[BATCH][8];

__global__ void __launch_bounds__(THREADS) reduce_kernel(const float4* __restrict__ x) {
    int b = blockIdx.y;
    const float4* __restrict__ xb = x + (size_t)b * N4;

    float a0=0.f,a1=0.f,a2=0.f,a3=0.f;
    float q00=0.f,q01=0.f,q02=0.f,q03=0.f;
    float q11=0.f,q12=0.f,q13=0.f;
    float q22=0.f,q23=0.f,q33=0.f;

    int base = blockIdx.x * THREADS + threadIdx.x;
    #pragma unroll 8
    for (int it = 0; it < ITERS; it++) {
        float4 v = __ldg(&xb[base + it * (RBLKS * THREADS)]);
        a0 += v.x; a1 += v.y; a2 += v.z; a3 += v.w;
        q00 = fmaf(v.x, v.x, q00);
        q01 = fmaf(v.x, v.y, q01);
        q02 = fmaf(v.x, v.z, q02);
        q03 = fmaf(v.x, v.w, q03);
        q11 = fmaf(v.y, v.y, q11);
        q12 = fmaf(v.y, v.z, q12);
        q13 = fmaf(v.y, v.w, q13);
        q22 = fmaf(v.z, v.z, q22);
        q23 = fmaf(v.z, v.w, q23);
        q33 = fmaf(v.w, v.w, q33);
    }

    float acc[14] = {a0,a1,a2,a3,q00,q01,q02,q03,q11,q12,q13,q22,q23,q33};

    #pragma unroll
    for (int k = 0; k < 14; k++) {
        #pragma unroll
        for (int off = 16; off > 0; off >>= 1)
            acc[k] += __shfl_down_sync(0xffffffffu, acc[k], off);
    }

    __shared__ double sh[8][14];
    int warp = threadIdx.x >> 5;
    int lane = threadIdx.x & 31;
    if (lane == 0) {
        #pragma unroll
        for (int k = 0; k < 14; k++) sh[warp][k] = (double)acc[k];
    }
    __syncthreads();

    if (threadIdx.x < 14) {
        double s = 0.0;
        #pragma unroll
        for (int w = 0; w < 8; w++) s += sh[w][threadIdx.x];
        g_part[b][blockIdx.x][threadIdx.x] = s;
    }
}

// one block per batch: sum partials (fp64), then single-thread fp32 Jacobi on E = A - I
__global__ void __launch_bounds__(64) solve_kernel() {
    int b = blockIdx.x;
    int t = threadIdx.x;

    __shared__ double sh[RBLKS][14];
    #pragma unroll
    for (int k = 0; k < 14; k++) sh[t][k] = g_part[b][t][k];
    __syncthreads();

    __shared__ double S[14];
    if (t < 14) {
        double s = 0.0;
        #pragma unroll 8
        for (int w = 0; w < RBLKS; w++) s += sh[w][t];
        S[t] = s;
    }
    __syncthreads();

    if (t != 0) return;

    const double N = (double)N4;
    double m[4];
    #pragma unroll
    for (int j = 0; j < 4; j++) m[j] = S[j] / N;

    double Q[4][4];
    Q[0][0]=S[4];  Q[0][1]=S[5];  Q[0][2]=S[6];  Q[0][3]=S[7];
    Q[1][1]=S[8];  Q[1][2]=S[9];  Q[1][3]=S[10];
    Q[2][2]=S[11]; Q[2][3]=S[12]; Q[3][3]=S[13];
    Q[1][0]=Q[0][1]; Q[2][0]=Q[0][2]; Q[3][0]=Q[0][3];
    Q[2][1]=Q[1][2]; Q[3][1]=Q[1][3]; Q[3][2]=Q[2][3];

    double inv_s[4];
    #pragma unroll
    for (int j = 0; j < 4; j++) {
        double var = Q[j][j] / N - m[j] * m[j];
        inv_s[j] = (var > 0.0) ? 1.0 / sqrt(var) : 0.0;
    }

    // E = A - I in fp32 (A = normalized gram; diag is 1 + O(eps), off-diag ~1/sqrt(N)).
    // fp32 Jacobi on E has ~1e-10 absolute entry resolution -> eigenvector error ~1e-7.
    float A[4][4];
    #pragma unroll
    for (int i = 0; i < 4; i++)
        #pragma unroll
        for (int j = 0; j < 4; j++) {
            double aij = (Q[i][j] - N * m[i] * m[j]) * inv_s[i] * inv_s[j];
            A[i][j] = (float)(i == j ? aij - 1.0 : aij);
        }

    float V[4][4] = {{1,0,0,0},{0,1,0,0},{0,0,1,0},{0,0,0,1}};
    for (int sweep = 0; sweep < 6; sweep++) {
        float offsum = fabsf(A[0][1]) + fabsf(A[0][2]) + fabsf(A[0][3])
                     + fabsf(A[1][2]) + fabsf(A[1][3]) + fabsf(A[2][3]);
        if (offsum == 0.0f) break;
        for (int p = 0; p < 3; p++) {
            for (int q = p + 1; q < 4; q++) {
                float apq = A[p][q];
                if (apq == 0.0f) continue;
                float theta = (A[q][q] - A[p][p]) / (2.0f * apq);
                float tt = copysignf(1.0f, theta) / (fabsf(theta) + sqrtf(theta * theta + 1.0f));
                float c = rsqrtf(tt * tt + 1.0f);
                float s = tt * c;
                float tau = s / (1.0f + c);
                for (int r = 0; r < 4; r++) {
                    if (r == p || r == q) continue;
                    float g = A[r][p], h = A[r][q];
                    A[r][p] = A[p][r] = g - s * (h + tau * g);
                    A[r][q] = A[q][r] = h + s * (g - tau * h);
                }
                A[p][p] -= tt * apq;
                A[q][q] += tt * apq;
                A[p][q] = A[q][p] = 0.0f;
                for (int r = 0; r < 4; r++) {
                    float g = V[r][p], h = V[r][q];
                    V[r][p] = g - s * (h + tau * g);
                    V[r][q] = h + s * (g - tau * h);
                }
            }
        }
    }

    int k = 0;
    float best = A[0][0];
    #pragma unroll
    for (int j = 1; j < 4; j++) if (A[j][j] > best) { best = A[j][j]; k = j; }

    double v[4];
    #pragma unroll
    for (int j = 0; j < 4; j++) v[j] = (double)V[j][k];
    double sv = v[0] + v[1] + v[2] + v[3];
    if (sv < 0.0) {
        #pragma unroll
        for (int j = 0; j < 4; j++) v[j] = -v[j];
    }

    double w[4], off = 0.0;
    #pragma unroll
    for (int j = 0; j < 4; j++) {
        w[j] = v[j] * inv_s[j];
        off += w[j] * m[j];
    }

    g_coef[b][0] = (float)w[0];
    g_coef[b][1] = (float)w[1];
    g_coef[b][2] = (float)w[2];
    g_coef[b][3] = (float)w[3];
    g_coef[b][4] = (float)off;
}

__global__ void __launch_bounds__(THREADS) out_kernel(const float4* __restrict__ x,
                                                      float* __restrict__ out) {
    int b = blockIdx.y;
    float w0 = g_coef[b][0];
    float w1 = g_coef[b][1];
    float w2 = g_coef[b][2];
    float w3 = g_coef[b][3];
    float off = g_coef[b][4];

    const float4* __restrict__ xb = x + (size_t)b * N4;
    float* __restrict__ ob = out + (size_t)b * N4;

    int base = blockIdx.x * THREADS + threadIdx.x;
    #pragma unroll 8
    for (int it = 0; it < ITERS; it++) {
        int i = base + it * (RBLKS * THREADS);
        float4 v = __ldg(&xb[i]);
        float r = fmaf(v.x, w0, fmaf(v.y, w1, fmaf(v.z, w2, fmaf(v.w, w3, -off))));
        // i = (h*128 + w)*16 + cg  ->  out[h/2][w/2][(h&1)*32 + (w&1)*16 + cg]
        int cg = i & 15;
        int ww = (i >> 4) & 127;
        int h  = i >> 11;
        int oc = ((h & 1) << 5) | ((ww & 1) << 4) | cg;
        int oidx = (((((h >> 1) << 6) | (ww >> 1)) << 6) | oc);
        ob[oidx] = r;
    }
}

extern "C" void kernel_launch(void* const* d_in, const int* in_sizes, int n_in,
                              void* d_out, int out_size) {
    const float4* x = (const float4*)d_in[0];
    float* out = (float*)d_out;

    reduce_kernel<<<dim3(RBLKS, BATCH), THREADS>>>(x);
    solve_kernel<<<BATCH, 64>>>();
    out_kernel<<<dim3(RBLKS, BATCH), THREADS>>>(x, out);
}